// round 7
// baseline (speedup 1.0000x reference)
#include <cuda_runtime.h>
#include <cstdio>
#include <cstdlib>
#include <math.h>

#define NN 100000
#define NE 1600000
#define F1 256
#define HIDD 64
#define NEGS 0.2f
#define NEGINF (-1e30f)

// ---------------- scratch (device globals; zero-init at load) --------------
__device__ __align__(16) int   d_cnt[NN];
__device__ __align__(16) int   d_rs[NN + 1];
__device__ __align__(16) int   d_cur[NN];
__device__ __align__(16) int   d_ssrc[NE];
__device__ __align__(16) int   d_seid[NE];
__device__ __align__(16) float d_slog1[NE * 4];
__device__ __align__(16) float d_slog2[NE];
__device__ __align__(16) float d_h1[NN * F1];
__device__ __align__(16) float d_als1[NN * 4];
__device__ __align__(16) float d_ald1[NN * 4];
__device__ __align__(16) float d_out1[NN * F1];
__device__ __align__(16) float d_h2[NN * HIDD];
__device__ __align__(16) float d_als2[NN];
__device__ __align__(16) float d_ald2[NN];
__device__ __align__(16) float d_out2[NN * HIDD];
__device__ __align__(16) float d_gv[NN * HIDD];
__device__ __align__(16) float d_c[8];

__device__ __forceinline__ float lrelu(float x) { return x > 0.f ? x : NEGS * x; }

__device__ __forceinline__ void mzmerge(float& m, float& z, float om, float oz) {
    float nm = fmaxf(m, om);
    float ea = (m == nm) ? 1.f : __expf(m - nm);
    float eb = (om == nm) ? 1.f : __expf(om - nm);
    z = z * ea + oz * eb;
    m = nm;
}
__device__ __forceinline__ void mzupd(float& m, float& z, float l) {
    float nm = fmaxf(m, l);
    z = z * __expf(m - nm) + __expf(l - nm);
    m = nm;
}

// ---------------- CSR build ----------------
__global__ void __launch_bounds__(256) k_zero() {
    int i = blockIdx.x * 256 + threadIdx.x;
    if (i < NN) d_cnt[i] = 0;
}

__global__ void __launch_bounds__(256) k_count(const int* __restrict__ ei) {
    int e = blockIdx.x * 256 + threadIdx.x;
    if (e < NE) {
        int d = ei[NE + e];
        if ((unsigned)d < NN) atomicAdd(&d_cnt[d], 1);
    }
}

__global__ void __launch_bounds__(256) k_scan() {
    __shared__ int sh[256];
    int t = threadIdx.x;
    const int CH = (NN + 255) / 256;  // 391
    int b0 = t * CH, b1 = min(NN, b0 + CH);
    int s = 0;
    for (int i = b0; i < b1; i++) s += d_cnt[i];
    sh[t] = s;
    __syncthreads();
    for (int off = 1; off < 256; off <<= 1) {
        int v = (t >= off) ? sh[t - off] : 0;
        __syncthreads();
        sh[t] += v;
        __syncthreads();
    }
    int run = sh[t] - s;  // exclusive base
    for (int i = b0; i < b1; i++) {
        d_rs[i] = run;
        d_cur[i] = run;
        run += d_cnt[i];
    }
    if (t == 255) d_rs[NN] = sh[255];
}

// ---------------- edge-score constants ----------------
__global__ void __launch_bounds__(256) k_const(const float* __restrict__ We1,
                                               const float* __restrict__ ae1,
                                               const float* __restrict__ We2,
                                               const float* __restrict__ ae2) {
    __shared__ float sh[256];
    int t = threadIdx.x;
    sh[t] = We1[t] * ae1[t];
    __syncthreads();
    if (t < 4) {
        float s = 0;
        for (int i = 0; i < 64; i++) s += sh[t * 64 + i];
        d_c[t] = s;
    }
    if (t == 4) {
        float s = 0;
        for (int i = 0; i < 64; i++) s += We2[i] * ae2[i];
        d_c[4] = s;
    }
}

// ---------------- layer-1 node transform + attention dots ----------------
__global__ void __launch_bounds__(256) k_node1(const float* __restrict__ x,
                                               const float* __restrict__ W1,
                                               const float* __restrict__ as1,
                                               const float* __restrict__ ad1) {
    int warp = threadIdx.x >> 5, lane = threadIdx.x & 31;
    int n = blockIdx.x * 8 + warp;
    if (n >= NN) return;
    float x0 = x[2 * n], x1 = x[2 * n + 1];
    int c0 = lane * 8;
    float h[8];
    float ps = 0.f, pd = 0.f;
#pragma unroll
    for (int j = 0; j < 8; j++) {
        int c = c0 + j;
        float hv = x0 * __ldg(&W1[c]) + x1 * __ldg(&W1[F1 + c]);
        h[j] = hv;
        ps += hv * __ldg(&as1[c]);
        pd += hv * __ldg(&ad1[c]);
    }
    float4* hp = (float4*)(d_h1 + (long)n * F1 + c0);
    hp[0] = make_float4(h[0], h[1], h[2], h[3]);
    hp[1] = make_float4(h[4], h[5], h[6], h[7]);
#pragma unroll
    for (int off = 4; off; off >>= 1) {
        ps += __shfl_down_sync(0xffffffffu, ps, off);
        pd += __shfl_down_sync(0xffffffffu, pd, off);
    }
    if ((lane & 7) == 0) {
        int head = lane >> 3;
        d_als1[n * 4 + head] = ps;
        d_ald1[n * 4 + head] = pd;
    }
}

// ---------------- fill CSR buckets + precompute layer-1 logits -------------
__global__ void __launch_bounds__(256) k_fill(const int* __restrict__ ei,
                                              const float* __restrict__ attr) {
    int e = blockIdx.x * 256 + threadIdx.x;
    if (e >= NE) return;
    int s = ei[e], dd = ei[NE + e];
    if ((unsigned)s >= NN || (unsigned)dd >= NN) return;
    int pos = atomicAdd(&d_cur[dd], 1);
    if ((unsigned)pos >= NE) return;
    d_ssrc[pos] = s;
    d_seid[pos] = e;
    float a = attr[e];
    float4 as_ = *(const float4*)(d_als1 + s * 4);
    float4 ad_ = *(const float4*)(d_ald1 + dd * 4);
    float4 c = *(const float4*)d_c;
    float4 lg;
    lg.x = lrelu(as_.x + ad_.x + a * c.x);
    lg.y = lrelu(as_.y + ad_.y + a * c.y);
    lg.z = lrelu(as_.z + ad_.z + a * c.z);
    lg.w = lrelu(as_.w + ad_.w + a * c.w);
    *(float4*)(d_slog1 + (long)pos * 4) = lg;
}

// ---------------- layer-1 fused softmax + aggregation (warp per node) ------
__global__ void __launch_bounds__(256) k_agg1(const float* __restrict__ b1) {
    int warp = threadIdx.x >> 5, lane = threadIdx.x & 31;
    int n = blockIdx.x * 8 + warp;
    if (n >= NN) return;
    int r0 = d_rs[n], r1 = d_rs[n + 1];

    float m0 = NEGINF, m1 = NEGINF, m2 = NEGINF, m3 = NEGINF;
    float z0 = 0.f, z1 = 0.f, z2 = 0.f, z3 = 0.f;
    for (int pos = r0 + lane; pos < r1; pos += 32) {
        float4 lg = *(const float4*)(d_slog1 + (long)pos * 4);
        mzupd(m0, z0, lg.x);
        mzupd(m1, z1, lg.y);
        mzupd(m2, z2, lg.z);
        mzupd(m3, z3, lg.w);
    }
#pragma unroll
    for (int off = 16; off; off >>= 1) {
        float om, oz;
        om = __shfl_xor_sync(0xffffffffu, m0, off); oz = __shfl_xor_sync(0xffffffffu, z0, off); mzmerge(m0, z0, om, oz);
        om = __shfl_xor_sync(0xffffffffu, m1, off); oz = __shfl_xor_sync(0xffffffffu, z1, off); mzmerge(m1, z1, om, oz);
        om = __shfl_xor_sync(0xffffffffu, m2, off); oz = __shfl_xor_sync(0xffffffffu, z2, off); mzmerge(m2, z2, om, oz);
        om = __shfl_xor_sync(0xffffffffu, m3, off); oz = __shfl_xor_sync(0xffffffffu, z3, off); mzmerge(m3, z3, om, oz);
    }
    int head = lane >> 3;
    float mh = (head == 0) ? m0 : (head == 1) ? m1 : (head == 2) ? m2 : m3;
    float zh = (head == 0) ? z0 : (head == 1) ? z1 : (head == 2) ? z2 : z3;
    float rz = 1.f / (zh + 1e-16f);

    float acc[8] = {0, 0, 0, 0, 0, 0, 0, 0};
    int c0 = lane * 8;
    for (int pos = r0; pos < r1; pos++) {
        int s = __ldg(&d_ssrc[pos]);
        float lg = __ldg(&d_slog1[(long)pos * 4 + head]);
        float al = __expf(lg - mh) * rz;
        const float4* hp = (const float4*)(d_h1 + (long)s * F1 + c0);
        float4 v0 = __ldg(hp);
        float4 v1 = __ldg(hp + 1);
        acc[0] += al * v0.x; acc[1] += al * v0.y; acc[2] += al * v0.z; acc[3] += al * v0.w;
        acc[4] += al * v1.x; acc[5] += al * v1.y; acc[6] += al * v1.z; acc[7] += al * v1.w;
    }
    float4 bb0 = __ldg((const float4*)(b1 + c0));
    float4 bb1 = __ldg((const float4*)(b1 + c0 + 4));
    float4* op = (float4*)(d_out1 + (long)n * F1 + c0);
    op[0] = make_float4(acc[0] + bb0.x, acc[1] + bb0.y, acc[2] + bb0.z, acc[3] + bb0.w);
    op[1] = make_float4(acc[4] + bb1.x, acc[5] + bb1.y, acc[6] + bb1.z, acc[7] + bb1.w);
}

// ---------------- tiled GEMM (A/C bound via template — device symbols!) ----
// AL=true : d_h2[N,64] = d_out1[N,256] @ B ; also als2/ald2 attention dots
// AL=false: d_gv[N,64] = d_out2[N,64] @ B
template <int K, bool AL>
__global__ void __launch_bounds__(256) k_gemm(const float* __restrict__ B,
                                              const float* __restrict__ av,
                                              const float* __restrict__ dv) {
    const float* A = AL ? d_out1 : d_out2;
    float* C = AL ? d_h2 : d_gv;
    __shared__ float sA[64][65];
    __shared__ float sB[64][64];
    __shared__ float sas[64], sad[64];
    int t = threadIdx.x;
    int r = t & 63, cg = t >> 6, c0 = cg * 16;
    int row0 = blockIdx.x * 64;
    float acc[16];
#pragma unroll
    for (int j = 0; j < 16; j++) acc[j] = 0.f;

    for (int kk = 0; kk < K; kk += 64) {
#pragma unroll
        for (int i = 0; i < 16; i++) {
            int lin = i * 256 + t;
            int rr = lin >> 6, cc = lin & 63;
            int grow = row0 + rr;
            sA[rr][cc] = (grow < NN) ? A[(long)grow * K + kk + cc] : 0.f;
            sB[rr][cc] = B[(long)(kk + rr) * 64 + cc];
        }
        __syncthreads();
#pragma unroll
        for (int k2 = 0; k2 < 64; k2++) {
            float a = sA[r][k2];
#pragma unroll
            for (int j = 0; j < 16; j++) acc[j] += a * sB[k2][c0 + j];
        }
        __syncthreads();
    }
    int grow = row0 + r;
    if (AL) {
        if (t < 64) { sas[t] = 0.f; sad[t] = 0.f; }
        __syncthreads();
        float pa = 0.f, pd = 0.f;
#pragma unroll
        for (int j = 0; j < 16; j++) {
            pa += acc[j] * __ldg(&av[c0 + j]);
            pd += acc[j] * __ldg(&dv[c0 + j]);
        }
        atomicAdd(&sas[r], pa);
        atomicAdd(&sad[r], pd);
        __syncthreads();
        if (t < 64 && row0 + t < NN) {
            d_als2[row0 + t] = sas[t];
            d_ald2[row0 + t] = sad[t];
        }
    }
    if (grow < NN) {
        float4* cp = (float4*)(C + (long)grow * 64 + c0);
        cp[0] = make_float4(acc[0], acc[1], acc[2], acc[3]);
        cp[1] = make_float4(acc[4], acc[5], acc[6], acc[7]);
        cp[2] = make_float4(acc[8], acc[9], acc[10], acc[11]);
        cp[3] = make_float4(acc[12], acc[13], acc[14], acc[15]);
    }
}

// ---------------- layer-2 logits (sorted positions) ----------------
__global__ void __launch_bounds__(256) k_log2(const int* __restrict__ ei,
                                              const float* __restrict__ attr) {
    int pos = blockIdx.x * 256 + threadIdx.x;
    if (pos >= NE) return;
    int e = d_seid[pos];
    if ((unsigned)e >= NE) { d_slog2[pos] = 0.f; return; }
    int s = d_ssrc[pos];
    int dd = ei[NE + e];
    if ((unsigned)s >= NN || (unsigned)dd >= NN) { d_slog2[pos] = 0.f; return; }
    float lg = d_als2[s] + d_ald2[dd] + attr[e] * d_c[4];
    d_slog2[pos] = lrelu(lg);
}

// ---------------- layer-2 fused softmax + aggregation ----------------
__global__ void __launch_bounds__(256) k_agg2(const float* __restrict__ b2) {
    int warp = threadIdx.x >> 5, lane = threadIdx.x & 31;
    int n = blockIdx.x * 8 + warp;
    if (n >= NN) return;
    int r0 = d_rs[n], r1 = d_rs[n + 1];
    float m = NEGINF, z = 0.f;
    for (int pos = r0 + lane; pos < r1; pos += 32) mzupd(m, z, d_slog2[pos]);
#pragma unroll
    for (int off = 16; off; off >>= 1) {
        float om = __shfl_xor_sync(0xffffffffu, m, off);
        float oz = __shfl_xor_sync(0xffffffffu, z, off);
        mzmerge(m, z, om, oz);
    }
    float rz = 1.f / (z + 1e-16f);
    float a0 = 0.f, a1 = 0.f;
    int c0 = lane * 2;
    for (int pos = r0; pos < r1; pos++) {
        int s = __ldg(&d_ssrc[pos]);
        float al = __expf(__ldg(&d_slog2[pos]) - m) * rz;
        float2 v = *(const float2*)(d_h2 + (long)s * 64 + c0);
        a0 += al * v.x;
        a1 += al * v.y;
    }
    float2 bb = __ldg((const float2*)(b2 + c0));
    *(float2*)(d_out2 + (long)n * 64 + c0) = make_float2(a0 + bb.x, a1 + bb.y);
}

// ---------------- final edge regressor (8 lanes per edge) ----------------
__global__ void __launch_bounds__(256) k_edge(const int* __restrict__ ei,
                                              const float* __restrict__ br1,
                                              const float* __restrict__ Wr2,
                                              const float* __restrict__ br2,
                                              float* __restrict__ out) {
    int t = blockIdx.x * 256 + threadIdx.x;
    int e = t >> 3;
    if (e >= NE) return;
    int o = t & 7;
    int s = __ldg(&ei[e]), dd = __ldg(&ei[NE + e]);
    if ((unsigned)s >= NN) s = 0;
    if ((unsigned)dd >= NN) dd = 0;
    int c0 = o * 8;
    const float4* gs = (const float4*)(d_gv + (long)s * 64 + c0);
    const float4* gd = (const float4*)(d_gv + (long)dd * 64 + c0);
    float4 s0 = __ldg(gs), s1 = __ldg(gs + 1);
    float4 t0 = __ldg(gd), t1 = __ldg(gd + 1);
    float4 w0 = __ldg((const float4*)(Wr2 + c0)), w1 = __ldg((const float4*)(Wr2 + c0 + 4));
    float4 r0 = __ldg((const float4*)(br1 + c0)), r1 = __ldg((const float4*)(br1 + c0 + 4));
    float p = 0.f;
    p += fmaxf(s0.x + t0.x + r0.x, 0.f) * w0.x;
    p += fmaxf(s0.y + t0.y + r0.y, 0.f) * w0.y;
    p += fmaxf(s0.z + t0.z + r0.z, 0.f) * w0.z;
    p += fmaxf(s0.w + t0.w + r0.w, 0.f) * w0.w;
    p += fmaxf(s1.x + t1.x + r1.x, 0.f) * w1.x;
    p += fmaxf(s1.y + t1.y + r1.y, 0.f) * w1.y;
    p += fmaxf(s1.z + t1.z + r1.z, 0.f) * w1.z;
    p += fmaxf(s1.w + t1.w + r1.w, 0.f) * w1.w;
#pragma unroll
    for (int off = 4; off; off >>= 1) p += __shfl_down_sync(0xffffffffu, p, off);
    if (o == 0) out[e] = p + __ldg(br2);
}

// ---------------- host diagnostics (static; no allocation) -----------------
static int   h_rs[1];
static float h_h2[2], h_gv[2], h_out[8];

// ---------------- launch ----------------
extern "C" void kernel_launch(void* const* d_in, const int* in_sizes, int n_in,
                              void* d_out, int out_size) {
    // insertion-order mapping (confirmed by round-5 diagnostics: alpha=0)
    const float* x    = (const float*)d_in[0];
    const int*   ei   = (const int*)d_in[1];
    const float* attr = (const float*)d_in[2];
    const float* W1   = (const float*)d_in[3];
    const float* We1  = (const float*)d_in[4];
    const float* as1  = (const float*)d_in[5];
    const float* ad1  = (const float*)d_in[6];
    const float* ae1  = (const float*)d_in[7];
    const float* b1   = (const float*)d_in[8];
    const float* W2   = (const float*)d_in[9];
    const float* We2  = (const float*)d_in[10];
    const float* as2  = (const float*)d_in[11];
    const float* ad2  = (const float*)d_in[12];
    const float* ae2  = (const float*)d_in[13];
    const float* b2   = (const float*)d_in[14];
    const float* Wr1  = (const float*)d_in[15];
    const float* br1  = (const float*)d_in[16];
    const float* Wr2  = (const float*)d_in[17];
    const float* br2  = (const float*)d_in[18];
    float* out = (float*)d_out;

    const int EB = (NE + 255) / 256;
    const int NB8 = (NN + 7) / 8;
    const int NB64 = (NN + 63) / 64;
    const int ZB = (NN + 255) / 256;

    k_zero<<<ZB, 256>>>();
    k_count<<<EB, 256>>>(ei);
    k_const<<<1, 256>>>(We1, ae1, We2, ae2);
    k_node1<<<NB8, 256>>>(x, W1, as1, ad1);
    k_scan<<<1, 256>>>();
    k_fill<<<EB, 256>>>(ei, attr);
    k_agg1<<<NB8, 256>>>(b1);
    k_gemm<F1, true><<<NB64, 256>>>(W2, as2, ad2);
    k_log2<<<EB, 256>>>(ei, attr);
    k_agg2<<<NB8, 256>>>(b2);
    k_gemm<HIDD, false><<<NB64, 256>>>(Wr1, (const float*)0, (const float*)0);
    k_edge<<<(NE * 8 + 255) / 256, 256>>>(ei, br1, Wr2, br2, out);

    // -------- slim health check: only on the non-capture correctness call --
    cudaStreamCaptureStatus cs = cudaStreamCaptureStatusNone;
    cudaStreamIsCapturing((cudaStream_t)0, &cs);
    if (cs != cudaStreamCaptureStatusNone) return;

    h_rs[0] = -777;
    cudaMemcpyFromSymbolAsync(h_rs, d_rs, 4, (size_t)NN * 4, cudaMemcpyDeviceToHost, 0);
    cudaMemcpyFromSymbolAsync(h_h2, d_h2, 8, 0, cudaMemcpyDeviceToHost, 0);
    cudaMemcpyFromSymbolAsync(h_gv, d_gv, 8, 0, cudaMemcpyDeviceToHost, 0);
    cudaMemcpyAsync(h_out, out, 32, cudaMemcpyDeviceToHost, 0);
    cudaError_t sticky = cudaGetLastError();

    float omax = 0.f;
    bool ofin = true;
    for (int i = 0; i < 8; i++) {
        if (!isfinite(h_out[i])) ofin = false;
        float a = fabsf(h_out[i]);
        if (a > omax) omax = a;
    }
    bool healthy = sticky == cudaSuccess && h_rs[0] == NE && ofin &&
                   omax > 1e-30f &&
                   (fabsf(h_h2[0]) + fabsf(h_h2[1])) > 0.f &&
                   (fabsf(h_gv[0]) + fabsf(h_gv[1])) > 0.f;
    if (healthy) return;

    for (int pass = 0; pass < 2; pass++) {
        FILE* f = pass ? stderr : stdout;
        fprintf(f, "DG sticky=%d(%s) rsN=%d h2=[%g %g] gv=[%g %g] out=[%g %g %g %g]\n",
                (int)sticky, cudaGetErrorString(sticky), h_rs[0],
                h_h2[0], h_h2[1], h_gv[0], h_gv[1],
                h_out[0], h_out[1], h_out[2], h_out[3]);
        fflush(f);
    }
    abort();
}

// round 8
// speedup vs baseline: 2.1161x; 2.1161x over previous
#include <cuda_runtime.h>
#include <cstdio>
#include <cstdlib>
#include <math.h>

#define NN 100000
#define NE 1600000
#define HIDD 64
#define NEGS 0.2f
#define NEGINF (-1e30f)

// ---------------- scratch (device globals; zero-init at load) --------------
__device__ __align__(16) int   d_cnt[NN];
__device__ __align__(16) int   d_rs[NN + 1];
__device__ __align__(16) int   d_cur[NN];
__device__ __align__(16) int   d_ssrc[NE];
__device__ __align__(16) float d_asort[NE];
__device__ __align__(16) float d_h2[NN * HIDD];
__device__ __align__(16) float d_als2[NN];
__device__ __align__(16) float d_ald2[NN];
__device__ __align__(16) float d_out2[NN * HIDD];
__device__ __align__(16) float d_gv[NN * HIDD];
// folded layer-1 constants
__device__ __align__(16) float d_u0[4], d_u1[4];   // as1 dots:  als1 = x0*u0+x1*u1
__device__ __align__(16) float d_v0[4], d_v1[4];   // ad1 dots
__device__ __align__(16) float d_c1[4];            // attr coeff per head (L1)
__device__ float d_c2s;                            // attr coeff (L2)
__device__ __align__(16) float d_G[512];           // [i][h][j] = W1(i,h,:)@W2(h,:,j)
__device__ __align__(16) float d_bvec[64];         // b1 @ W2

__device__ __forceinline__ float lrelu(float x) { return x > 0.f ? x : NEGS * x; }

__device__ __forceinline__ void mzmerge(float& m, float& z, float om, float oz) {
    float nm = fmaxf(m, om);
    float ea = (m == nm) ? 1.f : __expf(m - nm);
    float eb = (om == nm) ? 1.f : __expf(om - nm);
    z = z * ea + oz * eb;
    m = nm;
}
__device__ __forceinline__ void mzupd(float& m, float& z, float l) {
    float nm = fmaxf(m, l);
    z = z * __expf(m - nm) + __expf(l - nm);
    m = nm;
}

// ---------------- CSR build ----------------
__global__ void __launch_bounds__(256) k_zero() {
    int i = blockIdx.x * 256 + threadIdx.x;
    if (i < NN) d_cnt[i] = 0;
}

__global__ void __launch_bounds__(256) k_count(const int* __restrict__ ei) {
    int e = blockIdx.x * 256 + threadIdx.x;
    if (e < NE) {
        int d = ei[NE + e];
        if ((unsigned)d < NN) atomicAdd(&d_cnt[d], 1);
    }
}

__global__ void __launch_bounds__(512) k_scan() {
    __shared__ int sh[512];
    int t = threadIdx.x;
    const int CH = (NN + 511) / 512;  // 196
    int b0 = t * CH, b1 = min(NN, b0 + CH);
    int s = 0;
    for (int i = b0; i < b1; i++) s += d_cnt[i];
    sh[t] = s;
    __syncthreads();
    for (int off = 1; off < 512; off <<= 1) {
        int v = (t >= off) ? sh[t - off] : 0;
        __syncthreads();
        sh[t] += v;
        __syncthreads();
    }
    int run = sh[t] - s;  // exclusive base
    for (int i = b0; i < b1; i++) {
        d_rs[i] = run;
        d_cur[i] = run;
        run += d_cnt[i];
    }
    if (t == 511) d_rs[NN] = sh[511];
}

// ---------------- precompute folded constants ----------------
__global__ void __launch_bounds__(256) k_pre(const float* __restrict__ W1,
                                             const float* __restrict__ as1,
                                             const float* __restrict__ ad1,
                                             const float* __restrict__ We1,
                                             const float* __restrict__ ae1,
                                             const float* __restrict__ We2,
                                             const float* __restrict__ ae2,
                                             const float* __restrict__ b1,
                                             const float* __restrict__ W2) {
    int t = threadIdx.x;
    if (t < 4) {          // u0[h]
        float s = 0;
        for (int d = 0; d < 64; d++) s += W1[t * 64 + d] * as1[t * 64 + d];
        d_u0[t] = s;
    } else if (t < 8) {   // u1[h]
        int h = t - 4;
        float s = 0;
        for (int d = 0; d < 64; d++) s += W1[256 + h * 64 + d] * as1[h * 64 + d];
        d_u1[h] = s;
    } else if (t < 12) {  // v0[h]
        int h = t - 8;
        float s = 0;
        for (int d = 0; d < 64; d++) s += W1[h * 64 + d] * ad1[h * 64 + d];
        d_v0[h] = s;
    } else if (t < 16) {  // v1[h]
        int h = t - 12;
        float s = 0;
        for (int d = 0; d < 64; d++) s += W1[256 + h * 64 + d] * ad1[h * 64 + d];
        d_v1[h] = s;
    } else if (t < 20) {  // c1[h]
        int h = t - 16;
        float s = 0;
        for (int d = 0; d < 64; d++) s += We1[h * 64 + d] * ae1[h * 64 + d];
        d_c1[h] = s;
    } else if (t == 20) { // c2
        float s = 0;
        for (int d = 0; d < 64; d++) s += We2[d] * ae2[d];
        d_c2s = s;
    }
    if (t >= 64 && t < 128) {  // bvec[j] = b1 @ W2
        int j = t - 64;
        float s = 0;
        for (int c = 0; c < 256; c++) s += b1[c] * W2[c * 64 + j];
        d_bvec[j] = s;
    }
    // G[(i*4+h)*64+j] = sum_d W1[i*256+h*64+d] * W2[(h*64+d)*64+j]
#pragma unroll
    for (int rep = 0; rep < 2; rep++) {
        int idx = rep * 256 + t;
        int i = idx >> 8, rem = idx & 255, h = rem >> 6, j = rem & 63;
        float s = 0;
        for (int d = 0; d < 64; d++)
            s += W1[i * 256 + h * 64 + d] * W2[(h * 64 + d) * 64 + j];
        d_G[idx] = s;
    }
}

// ---------------- fill CSR buckets (sorted src + attr) ----------------
__global__ void __launch_bounds__(256) k_fill(const int* __restrict__ ei,
                                              const float* __restrict__ attr) {
    int e = blockIdx.x * 256 + threadIdx.x;
    if (e >= NE) return;
    int s = ei[e], dd = ei[NE + e];
    if ((unsigned)s >= NN || (unsigned)dd >= NN) return;
    int pos = atomicAdd(&d_cur[dd], 1);
    if ((unsigned)pos >= NE) return;
    d_ssrc[pos] = s;
    d_asort[pos] = attr[e];
}

// ---------------- layer-1 fused: softmax + rank-2 agg + @W2 + dots ---------
__global__ void __launch_bounds__(256) k_agg1(const float* __restrict__ x,
                                              const float* __restrict__ as2,
                                              const float* __restrict__ ad2) {
    int warp = threadIdx.x >> 5, lane = threadIdx.x & 31;
    int n = blockIdx.x * 8 + warp;
    if (n >= NN) return;
    int r0 = d_rs[n], r1 = d_rs[n + 1];

    float2 xn = __ldg((const float2*)x + n);
    float adh[4], u0[4], u1[4], c1[4];
#pragma unroll
    for (int h = 0; h < 4; h++) {
        u0[h] = d_u0[h]; u1[h] = d_u1[h]; c1[h] = d_c1[h];
        adh[h] = xn.x * d_v0[h] + xn.y * d_v1[h];
    }

    // pass 1: online softmax stats per head, lane-parallel over edges
    float m[4] = {NEGINF, NEGINF, NEGINF, NEGINF};
    float z[4] = {0, 0, 0, 0};
    for (int pos = r0 + lane; pos < r1; pos += 32) {
        int s = __ldg(&d_ssrc[pos]);
        float a = __ldg(&d_asort[pos]);
        float2 xs = __ldg((const float2*)x + s);
#pragma unroll
        for (int h = 0; h < 4; h++) {
            float lg = lrelu(xs.x * u0[h] + xs.y * u1[h] + adh[h] + a * c1[h]);
            mzupd(m[h], z[h], lg);
        }
    }
#pragma unroll
    for (int off = 16; off; off >>= 1) {
#pragma unroll
        for (int h = 0; h < 4; h++) {
            float om = __shfl_xor_sync(0xffffffffu, m[h], off);
            float oz = __shfl_xor_sync(0xffffffffu, z[h], off);
            mzmerge(m[h], z[h], om, oz);
        }
    }
    float rz[4];
#pragma unroll
    for (int h = 0; h < 4; h++) rz[h] = 1.f / (z[h] + 1e-16f);

    // pass 2: S[h][i] = sum_e alpha_eh * x_i[src]
    float acc[8] = {0, 0, 0, 0, 0, 0, 0, 0};
    for (int pos = r0 + lane; pos < r1; pos += 32) {
        int s = __ldg(&d_ssrc[pos]);
        float a = __ldg(&d_asort[pos]);
        float2 xs = __ldg((const float2*)x + s);
#pragma unroll
        for (int h = 0; h < 4; h++) {
            float lg = lrelu(xs.x * u0[h] + xs.y * u1[h] + adh[h] + a * c1[h]);
            float al = __expf(lg - m[h]) * rz[h];
            acc[2 * h] += al * xs.x;
            acc[2 * h + 1] += al * xs.y;
        }
    }
#pragma unroll
    for (int off = 16; off; off >>= 1)
#pragma unroll
        for (int q = 0; q < 8; q++)
            acc[q] += __shfl_xor_sync(0xffffffffu, acc[q], off);

    // epilogue: h2[n, 2*lane], h2[n, 2*lane+1]
    int j0 = 2 * lane;
    float h0 = __ldg(&d_bvec[j0]), h1v = __ldg(&d_bvec[j0 + 1]);
#pragma unroll
    for (int h = 0; h < 4; h++) {
#pragma unroll
        for (int i = 0; i < 2; i++) {
            float2 g = *(const float2*)(d_G + (i * 4 + h) * 64 + j0);
            float sv = acc[2 * h + i];
            h0 += sv * g.x;
            h1v += sv * g.y;
        }
    }
    *(float2*)(d_h2 + (long)n * 64 + j0) = make_float2(h0, h1v);

    // attention dots for layer 2
    float2 a2 = __ldg((const float2*)as2 + lane);
    float2 dd2 = __ldg((const float2*)ad2 + lane);
    float pa = h0 * a2.x + h1v * a2.y;
    float pd = h0 * dd2.x + h1v * dd2.y;
#pragma unroll
    for (int off = 16; off; off >>= 1) {
        pa += __shfl_xor_sync(0xffffffffu, pa, off);
        pd += __shfl_xor_sync(0xffffffffu, pd, off);
    }
    if (lane == 0) {
        d_als2[n] = pa;
        d_ald2[n] = pd;
    }
}

// ---------------- layer-2 fused softmax + aggregation ----------------
__global__ void __launch_bounds__(256) k_agg2(const float* __restrict__ b2) {
    int warp = threadIdx.x >> 5, lane = threadIdx.x & 31;
    int n = blockIdx.x * 8 + warp;
    if (n >= NN) return;
    int r0 = d_rs[n], r1 = d_rs[n + 1];
    float aldn = d_ald2[n];
    float c2 = d_c2s;

    float m = NEGINF, z = 0.f;
    for (int pos = r0 + lane; pos < r1; pos += 32) {
        int s = __ldg(&d_ssrc[pos]);
        float a = __ldg(&d_asort[pos]);
        mzupd(m, z, lrelu(__ldg(&d_als2[s]) + aldn + a * c2));
    }
#pragma unroll
    for (int off = 16; off; off >>= 1) {
        float om = __shfl_xor_sync(0xffffffffu, m, off);
        float oz = __shfl_xor_sync(0xffffffffu, z, off);
        mzmerge(m, z, om, oz);
    }
    float rz = 1.f / (z + 1e-16f);

    float a0 = 0.f, a1 = 0.f;
    int c0 = lane * 2;
    for (int pos = r0; pos < r1; pos++) {
        int s = __ldg(&d_ssrc[pos]);
        float a = __ldg(&d_asort[pos]);
        float lg = lrelu(__ldg(&d_als2[s]) + aldn + a * c2);
        float al = __expf(lg - m) * rz;
        float2 v = *(const float2*)(d_h2 + (long)s * 64 + c0);
        a0 += al * v.x;
        a1 += al * v.y;
    }
    float2 bb = __ldg((const float2*)(b2 + c0));
    *(float2*)(d_out2 + (long)n * 64 + c0) = make_float2(a0 + bb.x, a1 + bb.y);
}

// ---------------- GEMM: d_gv[N,64] = d_out2[N,64] @ Wr1 ----------------
__global__ void __launch_bounds__(256) k_gemm2(const float* __restrict__ B) {
    __shared__ float sA[64][65];
    __shared__ float sB[64][64];
    int t = threadIdx.x;
    int r = t & 63, cg = t >> 6, c0 = cg * 16;
    int row0 = blockIdx.x * 64;
    float acc[16];
#pragma unroll
    for (int j = 0; j < 16; j++) acc[j] = 0.f;

#pragma unroll
    for (int i = 0; i < 16; i++) {
        int lin = i * 256 + t;
        int rr = lin >> 6, cc = lin & 63;
        int grow = row0 + rr;
        sA[rr][cc] = (grow < NN) ? d_out2[(long)grow * 64 + cc] : 0.f;
        sB[rr][cc] = B[(long)rr * 64 + cc];
    }
    __syncthreads();
#pragma unroll
    for (int k2 = 0; k2 < 64; k2++) {
        float a = sA[r][k2];
#pragma unroll
        for (int j = 0; j < 16; j++) acc[j] += a * sB[k2][c0 + j];
    }
    int grow = row0 + r;
    if (grow < NN) {
        float4* cp = (float4*)(d_gv + (long)grow * 64 + c0);
        cp[0] = make_float4(acc[0], acc[1], acc[2], acc[3]);
        cp[1] = make_float4(acc[4], acc[5], acc[6], acc[7]);
        cp[2] = make_float4(acc[8], acc[9], acc[10], acc[11]);
        cp[3] = make_float4(acc[12], acc[13], acc[14], acc[15]);
    }
}

// ---------------- final edge regressor (8 lanes per edge) ----------------
__global__ void __launch_bounds__(256) k_edge(const int* __restrict__ ei,
                                              const float* __restrict__ br1,
                                              const float* __restrict__ Wr2,
                                              const float* __restrict__ br2,
                                              float* __restrict__ out) {
    int t = blockIdx.x * 256 + threadIdx.x;
    int e = t >> 3;
    if (e >= NE) return;
    int o = t & 7;
    int s = __ldg(&ei[e]), dd = __ldg(&ei[NE + e]);
    if ((unsigned)s >= NN) s = 0;
    if ((unsigned)dd >= NN) dd = 0;
    int c0 = o * 8;
    const float4* gs = (const float4*)(d_gv + (long)s * 64 + c0);
    const float4* gd = (const float4*)(d_gv + (long)dd * 64 + c0);
    float4 s0 = __ldg(gs), s1 = __ldg(gs + 1);
    float4 t0 = __ldg(gd), t1 = __ldg(gd + 1);
    float4 w0 = __ldg((const float4*)(Wr2 + c0)), w1 = __ldg((const float4*)(Wr2 + c0 + 4));
    float4 r0 = __ldg((const float4*)(br1 + c0)), r1 = __ldg((const float4*)(br1 + c0 + 4));
    float p = 0.f;
    p += fmaxf(s0.x + t0.x + r0.x, 0.f) * w0.x;
    p += fmaxf(s0.y + t0.y + r0.y, 0.f) * w0.y;
    p += fmaxf(s0.z + t0.z + r0.z, 0.f) * w0.z;
    p += fmaxf(s0.w + t0.w + r0.w, 0.f) * w0.w;
    p += fmaxf(s1.x + t1.x + r1.x, 0.f) * w1.x;
    p += fmaxf(s1.y + t1.y + r1.y, 0.f) * w1.y;
    p += fmaxf(s1.z + t1.z + r1.z, 0.f) * w1.z;
    p += fmaxf(s1.w + t1.w + r1.w, 0.f) * w1.w;
#pragma unroll
    for (int off = 4; off; off >>= 1) p += __shfl_down_sync(0xffffffffu, p, off);
    if (o == 0) out[e] = p + __ldg(br2);
}

// ---------------- host diagnostics (static; no allocation) -----------------
static int   h_rs[1];
static float h_h2[2], h_gv[2], h_out[8];

// ---------------- launch ----------------
extern "C" void kernel_launch(void* const* d_in, const int* in_sizes, int n_in,
                              void* d_out, int out_size) {
    // insertion-order mapping (confirmed by round-5 diagnostics)
    const float* x    = (const float*)d_in[0];
    const int*   ei   = (const int*)d_in[1];
    const float* attr = (const float*)d_in[2];
    const float* W1   = (const float*)d_in[3];
    const float* We1  = (const float*)d_in[4];
    const float* as1  = (const float*)d_in[5];
    const float* ad1  = (const float*)d_in[6];
    const float* ae1  = (const float*)d_in[7];
    const float* b1   = (const float*)d_in[8];
    const float* W2   = (const float*)d_in[9];
    const float* We2  = (const float*)d_in[10];
    const float* as2  = (const float*)d_in[11];
    const float* ad2  = (const float*)d_in[12];
    const float* ae2  = (const float*)d_in[13];
    const float* b2   = (const float*)d_in[14];
    const float* Wr1  = (const float*)d_in[15];
    const float* br1  = (const float*)d_in[16];
    const float* Wr2  = (const float*)d_in[17];
    const float* br2  = (const float*)d_in[18];
    float* out = (float*)d_out;

    const int EB = (NE + 255) / 256;
    const int NB8 = (NN + 7) / 8;
    const int NB64 = (NN + 63) / 64;
    const int ZB = (NN + 255) / 256;

    k_zero<<<ZB, 256>>>();
    k_count<<<EB, 256>>>(ei);
    k_pre<<<1, 256>>>(W1, as1, ad1, We1, ae1, We2, ae2, b1, W2);
    k_scan<<<1, 512>>>();
    k_fill<<<EB, 256>>>(ei, attr);
    k_agg1<<<NB8, 256>>>(x, as2, ad2);
    k_agg2<<<NB8, 256>>>(b2);
    k_gemm2<<<NB64, 256>>>(Wr1);
    k_edge<<<(NE * 8 + 255) / 256, 256>>>(ei, br1, Wr2, br2, out);

    // -------- slim health check: only on the non-capture correctness call --
    cudaStreamCaptureStatus cs = cudaStreamCaptureStatusNone;
    cudaStreamIsCapturing((cudaStream_t)0, &cs);
    if (cs != cudaStreamCaptureStatusNone) return;

    h_rs[0] = -777;
    cudaMemcpyFromSymbolAsync(h_rs, d_rs, 4, (size_t)NN * 4, cudaMemcpyDeviceToHost, 0);
    cudaMemcpyFromSymbolAsync(h_h2, d_h2, 8, 0, cudaMemcpyDeviceToHost, 0);
    cudaMemcpyFromSymbolAsync(h_gv, d_gv, 8, 0, cudaMemcpyDeviceToHost, 0);
    cudaMemcpyAsync(h_out, out, 32, cudaMemcpyDeviceToHost, 0);
    cudaError_t sticky = cudaGetLastError();

    float omax = 0.f;
    bool ofin = true;
    for (int i = 0; i < 8; i++) {
        if (!isfinite(h_out[i])) ofin = false;
        float a = fabsf(h_out[i]);
        if (a > omax) omax = a;
    }
    bool healthy = sticky == cudaSuccess && h_rs[0] == NE && ofin &&
                   omax > 1e-30f &&
                   (fabsf(h_h2[0]) + fabsf(h_h2[1])) > 0.f &&
                   (fabsf(h_gv[0]) + fabsf(h_gv[1])) > 0.f;
    if (healthy) return;

    for (int pass = 0; pass < 2; pass++) {
        FILE* f = pass ? stderr : stdout;
        fprintf(f, "DG sticky=%d(%s) rsN=%d h2=[%g %g] gv=[%g %g] out=[%g %g %g %g]\n",
                (int)sticky, cudaGetErrorString(sticky), h_rs[0],
                h_h2[0], h_h2[1], h_gv[0], h_gv[1],
                h_out[0], h_out[1], h_out[2], h_out[3]);
        fflush(f);
    }
    abort();
}